// round 11
// baseline (speedup 1.0000x reference)
#include <cuda_runtime.h>
#include <cuda_bf16.h>
#include <cstdint>

#define NN 50000
#define NE 800000
#define NG 128
#define DD 128
#define HH 512
#define H2 1024
#define NL 4
#define BN_SCALE 0.9999950000374997f

// ---------------- scratch (static device arrays) ----------------
__device__ float g_Z[NN * HH];
__device__ float g_Hb[NN * HH];
__device__ __nv_bfloat16 g_Ahi[NN * HH];
__device__ __nv_bfloat16 g_Alo[NN * HH];
__device__ __nv_bfloat16 g_Thi[NN * H2];
__device__ __nv_bfloat16 g_Tlo[NN * H2];
__device__ float g_vf[NG * HH];
__device__ float g_pl[NG * HH];
__device__ __nv_bfloat16 g_plhi[NG * HH];
__device__ __nv_bfloat16 g_pllo[NG * HH];
__device__ __nv_bfloat16 g_zvhi[NG * H2];
__device__ __nv_bfloat16 g_zvlo[NG * H2];
__device__ float g_cnt[NG];

#define WTOT 5898240
__device__ __nv_bfloat16 g_Whi[WTOT];
__device__ __nv_bfloat16 g_Wlo[WTOT];

// ---------------- helpers ----------------
__device__ __forceinline__ uint32_t smem_u32(const void* p) {
    uint32_t a;
    asm("{ .reg .u64 t; cvta.to.shared.u64 t, %1; cvt.u32.u64 %0, t; }" : "=r"(a) : "l"(p));
    return a;
}
#define SWZ(b) ((b) ^ (((b) >> 3) & 0x70))
// K-chunk=32 tile layout: two 64B rows per 128B line, then SW128 swizzle (conflict-free).
#define TPRE(r, b) ((uint32_t)((((r) >> 1) << 7) + (((r) & 1) << 6) + (b)))

__device__ __forceinline__ void cp_async16(uint32_t dst, const void* src, unsigned sz) {
    asm volatile("cp.async.cg.shared.global [%0], [%1], 16, %2;" :: "r"(dst), "l"(src), "r"(sz));
}
__device__ __forceinline__ void ldmx4(uint32_t* r, uint32_t addr) {
    asm volatile("ldmatrix.sync.aligned.m8n8.x4.shared.b16 {%0,%1,%2,%3}, [%4];"
                 : "=r"(r[0]), "=r"(r[1]), "=r"(r[2]), "=r"(r[3]) : "r"(addr));
}
__device__ __forceinline__ void mma_bf16(float* d, const uint32_t* a, uint32_t b0, uint32_t b1) {
    asm volatile("mma.sync.aligned.m16n8k16.row.col.f32.bf16.bf16.f32 "
                 "{%0,%1,%2,%3}, {%4,%5,%6,%7}, {%8,%9}, {%0,%1,%2,%3};"
                 : "+f"(d[0]), "+f"(d[1]), "+f"(d[2]), "+f"(d[3])
                 : "r"(a[0]), "r"(a[1]), "r"(a[2]), "r"(a[3]), "r"(b0), "r"(b1));
}

// ---------------- GEMM (frozen from R10): C[M,N] = epi( (Ahi+Alo)@(Bhi+Blo)^T ) ----------------
#define SMSTG 32768
#define ST_AHI 0
#define ST_ALO 8192
#define ST_BHI 16384
#define ST_BLO 24576
#define SM_TOTAL (3 * SMSTG)

__global__ void __launch_bounds__(256, 2)
k_gemm_mma(const __nv_bfloat16* __restrict__ Ahi, const __nv_bfloat16* __restrict__ Alo,
           const __nv_bfloat16* __restrict__ Bhi, const __nv_bfloat16* __restrict__ Blo,
           const float* __restrict__ bias, const float* __restrict__ gamma,
           const float* __restrict__ beta,
           float* __restrict__ C, __nv_bfloat16* __restrict__ Ohi, __nv_bfloat16* __restrict__ Olo,
           int M, int N, int K, int relu, int mode) {
    extern __shared__ char smem[];
    uint32_t sb = smem_u32(smem);
    int tid = threadIdx.x;
    int lane = tid & 31, wid = tid >> 5;
    int wm = (wid & 3) * 32;
    int wn = (wid >> 2) * 64;
    int rowBase = blockIdx.y * 128;
    int colBase = blockIdx.x * 128;

    float acc[2][8][4];
    #pragma unroll
    for (int i = 0; i < 2; i++)
        #pragma unroll
        for (int j = 0; j < 8; j++)
            #pragma unroll
            for (int k = 0; k < 4; k++) acc[i][j][k] = 0.0f;

    auto load_stage = [&](int buf, int k0) {
        uint32_t base = sb + buf * SMSTG;
        #pragma unroll
        for (int it = 0; it < 2; it++) {
            int idx = tid + it * 256;
            int row = idx >> 2;
            int ch = (idx & 3) * 16;
            uint32_t soff = SWZ(TPRE(row, ch));
            int gr = rowBase + row;
            unsigned sz = (gr < M) ? 16u : 0u;
            int grc = (gr < M) ? gr : 0;
            cp_async16(base + ST_AHI + soff, (const char*)(Ahi + (size_t)grc * K + k0) + ch, sz);
            cp_async16(base + ST_ALO + soff, (const char*)(Alo + (size_t)grc * K + k0) + ch, sz);
            int gc = colBase + row;
            cp_async16(base + ST_BHI + soff, (const char*)(Bhi + (size_t)gc * K + k0) + ch, 16u);
            cp_async16(base + ST_BLO + soff, (const char*)(Blo + (size_t)gc * K + k0) + ch, 16u);
        }
    };

    auto compute_stage = [&](int buf) {
        uint32_t aHiB = sb + buf * SMSTG + ST_AHI;
        uint32_t aLoB = sb + buf * SMSTG + ST_ALO;
        uint32_t bHiB = sb + buf * SMSTG + ST_BHI;
        uint32_t bLoB = sb + buf * SMSTG + ST_BLO;
        int mat = lane >> 3, l7 = lane & 7;
        #pragma unroll
        for (int ks = 0; ks < 2; ks++) {
            uint32_t ahi[2][4], alo[2][4];
            #pragma unroll
            for (int mt = 0; mt < 2; mt++) {
                int row = wm + mt * 16 + ((mat & 1) << 3) + l7;
                int byt = ks * 32 + ((mat >> 1) << 4);
                uint32_t off = SWZ(TPRE(row, byt));
                ldmx4(ahi[mt], aHiB + off);
                ldmx4(alo[mt], aLoB + off);
            }
            #pragma unroll
            for (int np = 0; np < 4; np++) {
                int row = wn + np * 16 + ((mat >> 1) << 3) + l7;
                int byt = ks * 32 + ((mat & 1) << 4);
                uint32_t off = SWZ(TPRE(row, byt));
                uint32_t bhi[4], blo[4];
                ldmx4(bhi, bHiB + off);
                ldmx4(blo, bLoB + off);
                #pragma unroll
                for (int mt = 0; mt < 2; mt++)
                    #pragma unroll
                    for (int h = 0; h < 2; h++)
                        mma_bf16(acc[mt][np * 2 + h], ahi[mt], bhi[2 * h], bhi[2 * h + 1]);
                #pragma unroll
                for (int mt = 0; mt < 2; mt++)
                    #pragma unroll
                    for (int h = 0; h < 2; h++)
                        mma_bf16(acc[mt][np * 2 + h], ahi[mt], blo[2 * h], blo[2 * h + 1]);
                #pragma unroll
                for (int mt = 0; mt < 2; mt++)
                    #pragma unroll
                    for (int h = 0; h < 2; h++)
                        mma_bf16(acc[mt][np * 2 + h], alo[mt], bhi[2 * h], bhi[2 * h + 1]);
            }
        }
    };

    int nk = K >> 5;
    load_stage(0, 0);
    asm volatile("cp.async.commit_group;" ::: "memory");
    load_stage(1, 32);
    asm volatile("cp.async.commit_group;" ::: "memory");

    for (int c = 0; c < nk; c++) {
        if (c + 1 < nk) asm volatile("cp.async.wait_group 1;" ::: "memory");
        else            asm volatile("cp.async.wait_group 0;" ::: "memory");
        __syncthreads();
        compute_stage(c % 3);
        if (c + 2 < nk) {
            load_stage((c + 2) % 3, (c + 2) * 32);
            asm volatile("cp.async.commit_group;" ::: "memory");
        }
    }

    int lm = lane >> 2;
    int ln = (lane & 3) * 2;
    #pragma unroll
    for (int mt = 0; mt < 2; mt++) {
        #pragma unroll
        for (int hr = 0; hr < 2; hr++) {
            int m = rowBase + wm + mt * 16 + hr * 8 + lm;
            if (m >= M) continue;
            #pragma unroll
            for (int nt = 0; nt < 8; nt++) {
                int n = colBase + wn + nt * 8 + ln;
                float v0 = acc[mt][nt][hr * 2 + 0];
                float v1 = acc[mt][nt][hr * 2 + 1];
                v0 = (v0 + __ldg(bias + n)) * (__ldg(gamma + n) * BN_SCALE) + __ldg(beta + n);
                v1 = (v1 + __ldg(bias + n + 1)) * (__ldg(gamma + n + 1) * BN_SCALE) + __ldg(beta + n + 1);
                if (relu) { v0 = fmaxf(v0, 0.f); v1 = fmaxf(v1, 0.f); }
                if (mode == 0) {
                    float2 o; o.x = v0; o.y = v1;
                    *(float2*)(C + (size_t)m * N + n) = o;
                } else {
                    uint32_t u0 = __float_as_uint(v0), u1 = __float_as_uint(v1);
                    uint32_t hv = __byte_perm(u0, u1, 0x7632);
                    float l0 = v0 - __uint_as_float(u0 & 0xFFFF0000u);
                    float l1 = v1 - __uint_as_float(u1 & 0xFFFF0000u);
                    uint32_t lv;
                    asm("cvt.rn.bf16x2.f32 %0, %1, %2;" : "=r"(lv) : "f"(l1), "f"(l0));
                    *(uint32_t*)(Ohi + (size_t)m * N + n) = hv;
                    *(uint32_t*)(Olo + (size_t)m * N + n) = lv;
                }
            }
        }
    }
}

// ---------------- prep: 12 weight segments + conv1 activation split, one launch ----------------
struct PrepArgs {
    const float* src[12];
    int K[12];
    int N[12];
    long off[12];
    const float4* act;
    uint32_t* acthi;
    uint32_t* actlo;
    int actn4;
};

__global__ void k_prep(PrepArgs a, __nv_bfloat16* __restrict__ hi,
                       __nv_bfloat16* __restrict__ lo) {
    int seg = blockIdx.y;
    int i = blockIdx.x * blockDim.x + threadIdx.x;
    if (seg < 12) {
        int K = a.K[seg], N = a.N[seg];
        if (i >= N * K) return;
        int n = i / K, k = i - n * K;
        float v = a.src[seg][(size_t)k * N + n];
        uint32_t u = __float_as_uint(v);
        long o = a.off[seg] + i;
        hi[o] = __ushort_as_bfloat16((unsigned short)(u >> 16));
        lo[o] = __float2bfloat16(v - __uint_as_float(u & 0xFFFF0000u));
    } else {
        if (i >= a.actn4) return;
        float4 v = a.act[i];
        uint32_t ux = __float_as_uint(v.x), uy = __float_as_uint(v.y);
        uint32_t uz = __float_as_uint(v.z), uw = __float_as_uint(v.w);
        uint32_t h0 = __byte_perm(ux, uy, 0x7632);
        uint32_t h1 = __byte_perm(uz, uw, 0x7632);
        float lx = v.x - __uint_as_float(ux & 0xFFFF0000u);
        float ly = v.y - __uint_as_float(uy & 0xFFFF0000u);
        float lz = v.z - __uint_as_float(uz & 0xFFFF0000u);
        float lw = v.w - __uint_as_float(uw & 0xFFFF0000u);
        uint32_t l0, l1;
        asm("cvt.rn.bf16x2.f32 %0, %1, %2;" : "=r"(l0) : "f"(ly), "f"(lx));
        asm("cvt.rn.bf16x2.f32 %0, %1, %2;" : "=r"(l1) : "f"(lw), "f"(lz));
        a.acthi[2 * i] = h0; a.acthi[2 * i + 1] = h1;
        a.actlo[2 * i] = l0; a.actlo[2 * i + 1] = l1;
    }
}

// ---------------- fp32 -> bf16 hi/lo split (activations) ----------------
__global__ void k_conv(const float4* __restrict__ in, uint32_t* __restrict__ hi,
                       uint32_t* __restrict__ lo, int n4) {
    int i = blockIdx.x * blockDim.x + threadIdx.x;
    if (i >= n4) return;
    float4 v = in[i];
    uint32_t ux = __float_as_uint(v.x), uy = __float_as_uint(v.y);
    uint32_t uz = __float_as_uint(v.z), uw = __float_as_uint(v.w);
    uint32_t h0 = __byte_perm(ux, uy, 0x7632);
    uint32_t h1 = __byte_perm(uz, uw, 0x7632);
    float lx = v.x - __uint_as_float(ux & 0xFFFF0000u);
    float ly = v.y - __uint_as_float(uy & 0xFFFF0000u);
    float lz = v.z - __uint_as_float(uz & 0xFFFF0000u);
    float lw = v.w - __uint_as_float(uw & 0xFFFF0000u);
    uint32_t l0, l1;
    asm("cvt.rn.bf16x2.f32 %0, %1, %2;" : "=r"(l0) : "f"(ly), "f"(lx));
    asm("cvt.rn.bf16x2.f32 %0, %1, %2;" : "=r"(l1) : "f"(lw), "f"(lz));
    hi[2 * i] = h0; hi[2 * i + 1] = h1;
    lo[2 * i] = l0; lo[2 * i + 1] = l1;
}

// ---------------- graph/pool kernels ----------------
__global__ void k_copy4(const float4* __restrict__ a, float4* __restrict__ b, int n4) {
    int i = blockIdx.x * blockDim.x + threadIdx.x;
    if (i < n4) b[i] = a[i];
}
__global__ void k_vfinit(const float* __restrict__ vemb, float* __restrict__ vf) {
    int i = blockIdx.x * blockDim.x + threadIdx.x;
    if (i < NG * HH) vf[i] = vemb[i & (HH - 1)];
}
// Z[i] = Hb[i] + vf[batch[i]]   (Hb NOT modified)
__global__ void k_initz(const float4* __restrict__ Hb, float4* __restrict__ Z,
                        const float4* __restrict__ vf, const int* __restrict__ batch) {
    int i = blockIdx.x * blockDim.x + threadIdx.x;
    if (i >= NN * (HH / 4)) return;
    int n = i >> 7, c = i & 127;
    int g = batch[n];
    float4 h = Hb[i];
    float4 v = vf[(g << 7) + c];
    h.x += v.x; h.y += v.y; h.z += v.z; h.w += v.w;
    Z[i] = h;
}
// conv1 scatter (no vn): Z[dst] += x[src]
__global__ void k_scatter(const float4* __restrict__ h, float4* __restrict__ Z,
                          const int* __restrict__ src, const int* __restrict__ dst,
                          int shift, int mask, int total) {
    int i = blockIdx.x * blockDim.x + threadIdx.x;
    if (i >= total) return;
    int e = i >> shift, c = i & mask;
    float4 v = h[(src[e] << shift) + c];
    atomicAdd(&Z[(dst[e] << shift) + c], v);
}
// HH scatter with fused vn: Z[dst] += Hb[src] + vf[batch[src]]
__global__ void k_scatter_vn(const float4* __restrict__ h, float4* __restrict__ Z,
                             const float4* __restrict__ vf,
                             const int* __restrict__ src, const int* __restrict__ dst,
                             const int* __restrict__ batch, int total) {
    int i = blockIdx.x * blockDim.x + threadIdx.x;
    if (i >= total) return;
    int e = i >> 7, c = i & 127;
    int s = src[e];
    int g = batch[s];
    float4 v = h[(s << 7) + c];
    float4 w = vf[(g << 7) + c];
    v.x += w.x; v.y += w.y; v.z += w.z; v.w += w.w;
    atomicAdd(&Z[(dst[e] << 7) + c], v);
}
__global__ void k_segsum(const float4* __restrict__ h, float4* __restrict__ acc,
                         const int* __restrict__ batch) {
    int i = blockIdx.x * blockDim.x + threadIdx.x;
    if (i >= NN * (HH / 4)) return;
    int n = i >> 7, c = i & 127;
    atomicAdd(&acc[(batch[n] << 7) + c], h[i]);
}
// zero out[NG*HH] and cnt[NG] in one launch
__global__ void k_zero2(float* __restrict__ out, float* __restrict__ cnt) {
    int i = blockIdx.x * blockDim.x + threadIdx.x;
    if (i < NG * HH) out[i] = 0.0f;
    if (i < NG) cnt[i] = 0.0f;
}
__global__ void k_count(float* __restrict__ cnt, const int* __restrict__ batch) {
    int i = blockIdx.x * blockDim.x + threadIdx.x;
    if (i < NN) atomicAdd(&cnt[batch[i]], 1.0f);
}
__global__ void k_div(float* __restrict__ out, const float* __restrict__ cnt) {
    int i = blockIdx.x * blockDim.x + threadIdx.x;
    if (i < NG * HH) out[i] /= fmaxf(cnt[i >> 9], 1.0f);
}

// weight offsets (elements) into g_Whi/g_Wlo
#define OFF_C1W1 0
#define OFF_C1W2 131072
#define OFF_CSW1 655360
#define OFF_CSW2 2752512
#define OFF_VW1  4849664
#define OFF_VW2  5373952

extern "C" void kernel_launch(void* const* d_in, const int* in_sizes, int n_in,
                              void* d_out, int out_size) {
    const float* x      = (const float*)d_in[0];
    const int*   ei     = (const int*)d_in[1];
    const int*   batch  = (const int*)d_in[2];
    const float* c1_W1  = (const float*)d_in[3];
    const float* c1_b1  = (const float*)d_in[4];
    const float* c1_g1  = (const float*)d_in[5];
    const float* c1_be1 = (const float*)d_in[6];
    const float* c1_W2  = (const float*)d_in[7];
    const float* c1_b2  = (const float*)d_in[8];
    const float* bn1_g  = (const float*)d_in[9];
    const float* bn1_b  = (const float*)d_in[10];
    const float* cs_W1  = (const float*)d_in[11];
    const float* cs_b1  = (const float*)d_in[12];
    const float* cs_g1  = (const float*)d_in[13];
    const float* cs_be1 = (const float*)d_in[14];
    const float* cs_W2  = (const float*)d_in[15];
    const float* cs_b2  = (const float*)d_in[16];
    const float* bns_g  = (const float*)d_in[17];
    const float* bns_b  = (const float*)d_in[18];
    const float* vemb   = (const float*)d_in[19];
    const float* v_W1   = (const float*)d_in[20];
    const float* v_b1   = (const float*)d_in[21];
    const float* v_g1   = (const float*)d_in[22];
    const float* v_be1  = (const float*)d_in[23];
    const float* v_W2   = (const float*)d_in[24];
    const float* v_b2   = (const float*)d_in[25];
    const float* v_g2   = (const float*)d_in[26];
    const float* v_be2  = (const float*)d_in[27];
    float* out = (float*)d_out;

    const int* srcI = ei;
    const int* dstI = ei + NE;

    float *Z, *Hb, *VF, *PL, *CNT;
    __nv_bfloat16 *Whi, *Wlo, *Ahi, *Alo, *Thi, *Tlo, *PLhi, *PLlo, *ZVhi, *ZVlo;
    cudaGetSymbolAddress((void**)&Z,    g_Z);
    cudaGetSymbolAddress((void**)&Hb,   g_Hb);
    cudaGetSymbolAddress((void**)&VF,   g_vf);
    cudaGetSymbolAddress((void**)&PL,   g_pl);
    cudaGetSymbolAddress((void**)&CNT,  g_cnt);
    cudaGetSymbolAddress((void**)&Whi,  g_Whi);
    cudaGetSymbolAddress((void**)&Wlo,  g_Wlo);
    cudaGetSymbolAddress((void**)&Ahi,  g_Ahi);
    cudaGetSymbolAddress((void**)&Alo,  g_Alo);
    cudaGetSymbolAddress((void**)&Thi,  g_Thi);
    cudaGetSymbolAddress((void**)&Tlo,  g_Tlo);
    cudaGetSymbolAddress((void**)&PLhi, g_plhi);
    cudaGetSymbolAddress((void**)&PLlo, g_pllo);
    cudaGetSymbolAddress((void**)&ZVhi, g_zvhi);
    cudaGetSymbolAddress((void**)&ZVlo, g_zvlo);

    cudaFuncSetAttribute(k_gemm_mma, cudaFuncAttributeMaxDynamicSharedMemorySize, SM_TOTAL);

    const int TB = 256;
    auto blks = [](int n) { return (n + 255) / 256; };

    // ---- launch 0-1: conv1 aggregation ----
    k_copy4<<<blks(NN * DD / 4), TB>>>((const float4*)x, (float4*)Z, NN * DD / 4);
    {
        int total = NE * (DD / 4);
        k_scatter<<<blks(total), TB>>>((const float4*)x, (float4*)Z, srcI, dstI, 5, 31, total);
    }

    // ---- launch 2: all weight prep + conv1 activation split ----
    PrepArgs pa;
    pa.src[0] = c1_W1;  pa.K[0] = DD; pa.N[0] = H2; pa.off[0] = OFF_C1W1;
    pa.src[1] = c1_W2;  pa.K[1] = H2; pa.N[1] = HH; pa.off[1] = OFF_C1W2;
    for (int i = 0; i < NL; i++) {
        pa.src[2 + i] = cs_W1 + (size_t)i * HH * H2;
        pa.K[2 + i] = HH; pa.N[2 + i] = H2; pa.off[2 + i] = OFF_CSW1 + (long)i * H2 * HH;
        pa.src[6 + i] = cs_W2 + (size_t)i * H2 * HH;
        pa.K[6 + i] = H2; pa.N[6 + i] = HH; pa.off[6 + i] = OFF_CSW2 + (long)i * H2 * HH;
    }
    pa.src[10] = v_W1; pa.K[10] = HH; pa.N[10] = H2; pa.off[10] = OFF_VW1;
    pa.src[11] = v_W2; pa.K[11] = H2; pa.N[11] = HH; pa.off[11] = OFF_VW2;
    pa.act = (const float4*)Z;
    pa.acthi = (uint32_t*)Ahi;
    pa.actlo = (uint32_t*)Alo;
    pa.actn4 = NN * DD / 4;
    k_prep<<<dim3(6250, 13), TB>>>(pa, Whi, Wlo);

    dim3 gN1(H2 / 128, (NN + 127) / 128);   // N=1024
    dim3 gN2(HH / 128, (NN + 127) / 128);   // N=512
    dim3 gv1(H2 / 128, 1);
    dim3 gv2(HH / 128, 1);

    // ---- launch 3: heavy GEMM (ncu target) ----
    k_gemm_mma<<<gN1, 256, SM_TOTAL>>>(Ahi, Alo, Whi + OFF_C1W1, Wlo + OFF_C1W1,
                                       c1_b1, c1_g1, c1_be1, nullptr, Thi, Tlo,
                                       NN, H2, DD, 1, 1);
    k_gemm_mma<<<gN2, 256, SM_TOTAL>>>(Thi, Tlo, Whi + OFF_C1W2, Wlo + OFF_C1W2,
                                       c1_b2, bn1_g, bn1_b, Hb, nullptr, nullptr,
                                       NN, HH, H2, 1, 0);

    // virtual node init (needed before layer loop)
    k_vfinit<<<blks(NG * HH), TB>>>(vemb, VF);

    // ---- L GIN layers with virtual node ----
    for (int i = 0; i < NL; i++) {
        // Z = Hb + vf[batch]  (Hb untouched; vn folded into scatter below)
        k_initz<<<blks(NN * (HH / 4)), TB>>>((const float4*)Hb, (float4*)Z, (const float4*)VF, batch);
        {
            int total = NE * (HH / 4);
            k_scatter_vn<<<blks(total), TB>>>((const float4*)Hb, (float4*)Z, (const float4*)VF,
                                              srcI, dstI, batch, total);
        }
        k_conv<<<blks(NN * HH / 4), TB>>>((const float4*)Z, (uint32_t*)Ahi, (uint32_t*)Alo, NN * HH / 4);
        k_gemm_mma<<<gN1, 256, SM_TOTAL>>>(Ahi, Alo,
                                           Whi + OFF_CSW1 + (size_t)i * H2 * HH,
                                           Wlo + OFF_CSW1 + (size_t)i * H2 * HH,
                                           cs_b1 + i * H2, cs_g1 + i * H2, cs_be1 + i * H2,
                                           nullptr, Thi, Tlo, NN, H2, HH, 1, 1);
        k_gemm_mma<<<gN2, 256, SM_TOTAL>>>(Thi, Tlo,
                                           Whi + OFF_CSW2 + (size_t)i * H2 * HH,
                                           Wlo + OFF_CSW2 + (size_t)i * H2 * HH,
                                           cs_b2 + i * HH, bns_g + i * HH, bns_b + i * HH,
                                           Hb, nullptr, nullptr, NN, HH, H2,
                                           (i < NL - 1) ? 1 : 0, 0);
        if (i < NL - 1) {
            k_copy4<<<blks(NG * HH / 4), TB>>>((const float4*)VF, (float4*)PL, NG * HH / 4);
            k_segsum<<<blks(NN * (HH / 4)), TB>>>((const float4*)Hb, (float4*)PL, batch);
            k_conv<<<blks(NG * HH / 4), TB>>>((const float4*)PL, (uint32_t*)PLhi, (uint32_t*)PLlo, NG * HH / 4);
            k_gemm_mma<<<gv1, 256, SM_TOTAL>>>(PLhi, PLlo, Whi + OFF_VW1, Wlo + OFF_VW1,
                                               v_b1, v_g1, v_be1, nullptr, ZVhi, ZVlo,
                                               NG, H2, HH, 1, 1);
            k_gemm_mma<<<gv2, 256, SM_TOTAL>>>(ZVhi, ZVlo, Whi + OFF_VW2, Wlo + OFF_VW2,
                                               v_b2, v_g2, v_be2, VF, nullptr, nullptr,
                                               NG, HH, H2, 1, 0);
        }
    }

    // ---- readout: mean pool ----
    k_zero2<<<blks(NG * HH), TB>>>(out, CNT);
    k_segsum<<<blks(NN * (HH / 4)), TB>>>((const float4*)Hb, (float4*)out, batch);
    k_count<<<blks(NN), TB>>>(CNT, batch);
    k_div<<<blks(NG * HH), TB>>>(out, CNT);
}

// round 13
// speedup vs baseline: 1.3477x; 1.3477x over previous
#include <cuda_runtime.h>
#include <cuda_bf16.h>
#include <cstdint>

#define NN 50000
#define NE 800000
#define NG 128
#define DD 128
#define HH 512
#define H2 1024
#define NL 4
#define BN_SCALE 0.9999950000374997f

// ---------------- scratch (static device arrays) ----------------
__device__ float g_Z[NN * HH];                // Hb + vf[batch] (layer conv input, fp32)
__device__ float g_Hb[NN * HH];
__device__ __nv_bfloat16 g_Ahi[NN * HH];
__device__ __nv_bfloat16 g_Alo[NN * HH];
__device__ __nv_bfloat16 g_Thi[NN * H2];
__device__ __nv_bfloat16 g_Tlo[NN * H2];
__device__ float g_vf[NG * HH];
__device__ __nv_bfloat16 g_plhi[NG * HH];
__device__ __nv_bfloat16 g_pllo[NG * HH];
__device__ __nv_bfloat16 g_zvhi[NG * H2];
__device__ __nv_bfloat16 g_zvlo[NG * H2];

// CSR of the edge list (rebuilt every launch; deterministic inputs)
__device__ int g_off[NN + 1];
__device__ int g_cur[NN];
__device__ int g_esrc[NE];
__device__ int g_gs[NG + 1];

#define WTOT 5898240
__device__ __nv_bfloat16 g_Whi[WTOT];
__device__ __nv_bfloat16 g_Wlo[WTOT];

// ---------------- helpers ----------------
__device__ __forceinline__ uint32_t smem_u32(const void* p) {
    uint32_t a;
    asm("{ .reg .u64 t; cvta.to.shared.u64 t, %1; cvt.u32.u64 %0, t; }" : "=r"(a) : "l"(p));
    return a;
}
#define SWZ(b) ((b) ^ (((b) >> 3) & 0x70))
#define TPRE(r, b) ((uint32_t)((((r) >> 1) << 7) + (((r) & 1) << 6) + (b)))

__device__ __forceinline__ void cp_async16(uint32_t dst, const void* src, unsigned sz) {
    asm volatile("cp.async.cg.shared.global [%0], [%1], 16, %2;" :: "r"(dst), "l"(src), "r"(sz));
}
__device__ __forceinline__ void ldmx4(uint32_t* r, uint32_t addr) {
    asm volatile("ldmatrix.sync.aligned.m8n8.x4.shared.b16 {%0,%1,%2,%3}, [%4];"
                 : "=r"(r[0]), "=r"(r[1]), "=r"(r[2]), "=r"(r[3]) : "r"(addr));
}
__device__ __forceinline__ void mma_bf16(float* d, const uint32_t* a, uint32_t b0, uint32_t b1) {
    asm volatile("mma.sync.aligned.m16n8k16.row.col.f32.bf16.bf16.f32 "
                 "{%0,%1,%2,%3}, {%4,%5,%6,%7}, {%8,%9}, {%0,%1,%2,%3};"
                 : "+f"(d[0]), "+f"(d[1]), "+f"(d[2]), "+f"(d[3])
                 : "r"(a[0]), "r"(a[1]), "r"(a[2]), "r"(a[3]), "r"(b0), "r"(b1));
}
__device__ __forceinline__ void split_store(uint32_t* hi, uint32_t* lo, long idx2,
                                            float a, float b) {
    uint32_t ua = __float_as_uint(a), ub = __float_as_uint(b);
    uint32_t hv = __byte_perm(ua, ub, 0x7632);
    float la = a - __uint_as_float(ua & 0xFFFF0000u);
    float lb = b - __uint_as_float(ub & 0xFFFF0000u);
    uint32_t lv;
    asm("cvt.rn.bf16x2.f32 %0, %1, %2;" : "=r"(lv) : "f"(lb), "f"(la));
    hi[idx2] = hv;
    lo[idx2] = lv;
}

// ---------------- GEMM (frozen from R10) ----------------
#define SMSTG 32768
#define ST_AHI 0
#define ST_ALO 8192
#define ST_BHI 16384
#define ST_BLO 24576
#define SM_TOTAL (3 * SMSTG)

__global__ void __launch_bounds__(256, 2)
k_gemm_mma(const __nv_bfloat16* __restrict__ Ahi, const __nv_bfloat16* __restrict__ Alo,
           const __nv_bfloat16* __restrict__ Bhi, const __nv_bfloat16* __restrict__ Blo,
           const float* __restrict__ bias, const float* __restrict__ gamma,
           const float* __restrict__ beta,
           float* __restrict__ C, __nv_bfloat16* __restrict__ Ohi, __nv_bfloat16* __restrict__ Olo,
           int M, int N, int K, int relu, int mode) {
    extern __shared__ char smem[];
    uint32_t sb = smem_u32(smem);
    int tid = threadIdx.x;
    int lane = tid & 31, wid = tid >> 5;
    int wm = (wid & 3) * 32;
    int wn = (wid >> 2) * 64;
    int rowBase = blockIdx.y * 128;
    int colBase = blockIdx.x * 128;

    float acc[2][8][4];
    #pragma unroll
    for (int i = 0; i < 2; i++)
        #pragma unroll
        for (int j = 0; j < 8; j++)
            #pragma unroll
            for (int k = 0; k < 4; k++) acc[i][j][k] = 0.0f;

    auto load_stage = [&](int buf, int k0) {
        uint32_t base = sb + buf * SMSTG;
        #pragma unroll
        for (int it = 0; it < 2; it++) {
            int idx = tid + it * 256;
            int row = idx >> 2;
            int ch = (idx & 3) * 16;
            uint32_t soff = SWZ(TPRE(row, ch));
            int gr = rowBase + row;
            unsigned sz = (gr < M) ? 16u : 0u;
            int grc = (gr < M) ? gr : 0;
            cp_async16(base + ST_AHI + soff, (const char*)(Ahi + (size_t)grc * K + k0) + ch, sz);
            cp_async16(base + ST_ALO + soff, (const char*)(Alo + (size_t)grc * K + k0) + ch, sz);
            int gc = colBase + row;
            cp_async16(base + ST_BHI + soff, (const char*)(Bhi + (size_t)gc * K + k0) + ch, 16u);
            cp_async16(base + ST_BLO + soff, (const char*)(Blo + (size_t)gc * K + k0) + ch, 16u);
        }
    };

    auto compute_stage = [&](int buf) {
        uint32_t aHiB = sb + buf * SMSTG + ST_AHI;
        uint32_t aLoB = sb + buf * SMSTG + ST_ALO;
        uint32_t bHiB = sb + buf * SMSTG + ST_BHI;
        uint32_t bLoB = sb + buf * SMSTG + ST_BLO;
        int mat = lane >> 3, l7 = lane & 7;
        #pragma unroll
        for (int ks = 0; ks < 2; ks++) {
            uint32_t ahi[2][4], alo[2][4];
            #pragma unroll
            for (int mt = 0; mt < 2; mt++) {
                int row = wm + mt * 16 + ((mat & 1) << 3) + l7;
                int byt = ks * 32 + ((mat >> 1) << 4);
                uint32_t off = SWZ(TPRE(row, byt));
                ldmx4(ahi[mt], aHiB + off);
                ldmx4(alo[mt], aLoB + off);
            }
            #pragma unroll
            for (int np = 0; np < 4; np++) {
                int row = wn + np * 16 + ((mat >> 1) << 3) + l7;
                int byt = ks * 32 + ((mat & 1) << 4);
                uint32_t off = SWZ(TPRE(row, byt));
                uint32_t bhi[4], blo[4];
                ldmx4(bhi, bHiB + off);
                ldmx4(blo, bLoB + off);
                #pragma unroll
                for (int mt = 0; mt < 2; mt++)
                    #pragma unroll
                    for (int h = 0; h < 2; h++)
                        mma_bf16(acc[mt][np * 2 + h], ahi[mt], bhi[2 * h], bhi[2 * h + 1]);
                #pragma unroll
                for (int mt = 0; mt < 2; mt++)
                    #pragma unroll
                    for (int h = 0; h < 2; h++)
                        mma_bf16(acc[mt][np * 2 + h], ahi[mt], blo[2 * h], blo[2 * h + 1]);
                #pragma unroll
                for (int mt = 0; mt < 2; mt++)
                    #pragma unroll
                    for (int h = 0; h < 2; h++)
                        mma_bf16(acc[mt][np * 2 + h], alo[mt], bhi[2 * h], bhi[2 * h + 1]);
            }
        }
    };

    int nk = K >> 5;
    load_stage(0, 0);
    asm volatile("cp.async.commit_group;" ::: "memory");
    load_stage(1, 32);
    asm volatile("cp.async.commit_group;" ::: "memory");

    for (int c = 0; c < nk; c++) {
        if (c + 1 < nk) asm volatile("cp.async.wait_group 1;" ::: "memory");
        else            asm volatile("cp.async.wait_group 0;" ::: "memory");
        __syncthreads();
        compute_stage(c % 3);
        if (c + 2 < nk) {
            load_stage((c + 2) % 3, (c + 2) * 32);
            asm volatile("cp.async.commit_group;" ::: "memory");
        }
    }

    int lm = lane >> 2;
    int ln = (lane & 3) * 2;
    #pragma unroll
    for (int mt = 0; mt < 2; mt++) {
        #pragma unroll
        for (int hr = 0; hr < 2; hr++) {
            int m = rowBase + wm + mt * 16 + hr * 8 + lm;
            if (m >= M) continue;
            #pragma unroll
            for (int nt = 0; nt < 8; nt++) {
                int n = colBase + wn + nt * 8 + ln;
                float v0 = acc[mt][nt][hr * 2 + 0];
                float v1 = acc[mt][nt][hr * 2 + 1];
                v0 = (v0 + __ldg(bias + n)) * (__ldg(gamma + n) * BN_SCALE) + __ldg(beta + n);
                v1 = (v1 + __ldg(bias + n + 1)) * (__ldg(gamma + n + 1) * BN_SCALE) + __ldg(beta + n + 1);
                if (relu) { v0 = fmaxf(v0, 0.f); v1 = fmaxf(v1, 0.f); }
                if (mode == 0) {
                    float2 o; o.x = v0; o.y = v1;
                    *(float2*)(C + (size_t)m * N + n) = o;
                } else {
                    split_store((uint32_t*)Ohi, (uint32_t*)Olo, ((size_t)m * N + n) >> 1, v0, v1);
                }
            }
        }
    }
}

// ---------------- CSR build ----------------
__global__ void k_csr0(const int* __restrict__ batch) {
    int i = blockIdx.x * blockDim.x + threadIdx.x;
    if (i <= NN) g_off[i] = 0;
    if (i <= NG) {
        if (i == NG) g_gs[NG] = NN;
        else {
            // lower_bound(batch, i)
            int lo = 0, hi = NN;
            while (lo < hi) {
                int mid = (lo + hi) >> 1;
                if (batch[mid] < i) lo = mid + 1; else hi = mid;
            }
            g_gs[i] = lo;
        }
    }
}
__global__ void k_deg(const int* __restrict__ dst) {
    int e = blockIdx.x * blockDim.x + threadIdx.x;
    if (e < NE) atomicAdd(&g_off[dst[e]], 1);
}
// single-block exclusive scan over g_off[0..NN], copy into g_cur
__global__ void __launch_bounds__(1024) k_scan() {
    __shared__ int part[1024];
    int t = threadIdx.x;
    const int CH = (NN + 1 + 1023) / 1024;   // 49
    int base = t * CH;
    int vals[49];
    int s = 0;
    #pragma unroll 1
    for (int j = 0; j < CH; j++) {
        int idx = base + j;
        int v = (idx <= NN) ? g_off[idx] : 0;
        vals[j] = s;     // local exclusive
        s += v;
    }
    part[t] = s;
    __syncthreads();
    // Hillis-Steele inclusive scan on part
    #pragma unroll
    for (int d = 1; d < 1024; d <<= 1) {
        int v = (t >= d) ? part[t - d] : 0;
        __syncthreads();
        part[t] += v;
        __syncthreads();
    }
    int pre = (t == 0) ? 0 : part[t - 1];
    #pragma unroll 1
    for (int j = 0; j < CH; j++) {
        int idx = base + j;
        if (idx <= NN) {
            int o = pre + vals[j];
            g_off[idx] = o;
            if (idx < NN) g_cur[idx] = o;
        }
    }
}
__global__ void k_fill(const int* __restrict__ src, const int* __restrict__ dst) {
    int e = blockIdx.x * blockDim.x + threadIdx.x;
    if (e >= NE) return;
    int pos = atomicAdd(&g_cur[dst[e]], 1);
    g_esrc[pos] = src[e];
}

// ---------------- aggregation (no atomics) ----------------
// conv1: warp per node (D=128 floats = 32 float4 per row); out = split(x[n] + sum x[src])
__global__ void __launch_bounds__(128) k_aggr1(const float4* __restrict__ X,
                                               uint32_t* __restrict__ hi, uint32_t* __restrict__ lo) {
    int n = blockIdx.x * 4 + (threadIdx.x >> 5);
    int c = threadIdx.x & 31;
    if (n >= NN) return;
    float4 acc = X[n * 32 + c];
    int e0 = g_off[n], e1 = g_off[n + 1];
    for (int e = e0; e < e1; e++) {
        int s = g_esrc[e];
        float4 v = X[s * 32 + c];
        acc.x += v.x; acc.y += v.y; acc.z += v.z; acc.w += v.w;
    }
    long i2 = (long)n * 64 + c * 2;
    split_store(hi, lo, i2, acc.x, acc.y);
    split_store(hi, lo, i2 + 1, acc.z, acc.w);
}
// layers: block(128) per node (HH=512 floats = 128 float4); out = split(Zv[n] + sum Zv[src])
__global__ void __launch_bounds__(128) k_aggrH(const float4* __restrict__ Zv,
                                               uint32_t* __restrict__ hi, uint32_t* __restrict__ lo) {
    int n = blockIdx.x;
    int c = threadIdx.x;
    float4 acc = Zv[n * 128 + c];
    int e0 = g_off[n], e1 = g_off[n + 1];
    for (int e = e0; e < e1; e++) {
        int s = g_esrc[e];
        float4 v = Zv[s * 128 + c];
        acc.x += v.x; acc.y += v.y; acc.z += v.z; acc.w += v.w;
    }
    long i2 = (long)n * 256 + c * 2;
    split_store(hi, lo, i2, acc.x, acc.y);
    split_store(hi, lo, i2 + 1, acc.z, acc.w);
}

// Z = Hb + vf[batch]  (Hb untouched)
__global__ void k_addv(const float4* __restrict__ Hb, float4* __restrict__ Z,
                       const float4* __restrict__ vf, const int* __restrict__ batch) {
    int i = blockIdx.x * blockDim.x + threadIdx.x;
    if (i >= NN * (HH / 4)) return;
    int n = i >> 7, c = i & 127;
    int g = batch[n];
    float4 h = Hb[i];
    float4 v = vf[(g << 7) + c];
    h.x += v.x; h.y += v.y; h.z += v.z; h.w += v.w;
    Z[i] = h;
}

// virtual pool: PL = split(vf[g] + sum_{n in graph g} Hb[n]); block per graph
__global__ void __launch_bounds__(128) k_poolv(const float4* __restrict__ Hb,
                                               const float4* __restrict__ vf,
                                               uint32_t* __restrict__ hi, uint32_t* __restrict__ lo) {
    int g = blockIdx.x;
    int c = threadIdx.x;
    float4 acc = vf[g * 128 + c];
    int n0 = g_gs[g], n1 = g_gs[g + 1];
    for (int n = n0; n < n1; n++) {
        float4 v = Hb[n * 128 + c];
        acc.x += v.x; acc.y += v.y; acc.z += v.z; acc.w += v.w;
    }
    long i2 = (long)g * 256 + c * 2;
    split_store(hi, lo, i2, acc.x, acc.y);
    split_store(hi, lo, i2 + 1, acc.z, acc.w);
}
// readout: out[g] = (sum Hb[n]) / max(count,1); block per graph
__global__ void __launch_bounds__(128) k_poolout(const float4* __restrict__ Hb,
                                                 float4* __restrict__ out) {
    int g = blockIdx.x;
    int c = threadIdx.x;
    int n0 = g_gs[g], n1 = g_gs[g + 1];
    float4 acc = make_float4(0.f, 0.f, 0.f, 0.f);
    for (int n = n0; n < n1; n++) {
        float4 v = Hb[n * 128 + c];
        acc.x += v.x; acc.y += v.y; acc.z += v.z; acc.w += v.w;
    }
    float inv = 1.0f / fmaxf((float)(n1 - n0), 1.0f);
    acc.x *= inv; acc.y *= inv; acc.z *= inv; acc.w *= inv;
    out[g * 128 + c] = acc;
}

// ---------------- prep: 12 weight segments ----------------
struct PrepArgs {
    const float* src[12];
    int K[12];
    int N[12];
    long off[12];
};
__global__ void k_prep(PrepArgs a, __nv_bfloat16* __restrict__ hi,
                       __nv_bfloat16* __restrict__ lo) {
    int seg = blockIdx.y;
    int i = blockIdx.x * blockDim.x + threadIdx.x;
    int K = a.K[seg], N = a.N[seg];
    if (i >= N * K) return;
    int n = i / K, k = i - n * K;
    float v = a.src[seg][(size_t)k * N + n];
    uint32_t u = __float_as_uint(v);
    long o = a.off[seg] + i;
    hi[o] = __ushort_as_bfloat16((unsigned short)(u >> 16));
    lo[o] = __float2bfloat16(v - __uint_as_float(u & 0xFFFF0000u));
}

__global__ void k_vfinit(const float* __restrict__ vemb, float* __restrict__ vf) {
    int i = blockIdx.x * blockDim.x + threadIdx.x;
    if (i < NG * HH) vf[i] = vemb[i & (HH - 1)];
}

// weight offsets (elements) into g_Whi/g_Wlo
#define OFF_C1W1 0
#define OFF_C1W2 131072
#define OFF_CSW1 655360
#define OFF_CSW2 2752512
#define OFF_VW1  4849664
#define OFF_VW2  5373952

extern "C" void kernel_launch(void* const* d_in, const int* in_sizes, int n_in,
                              void* d_out, int out_size) {
    const float* x      = (const float*)d_in[0];
    const int*   ei     = (const int*)d_in[1];
    const int*   batch  = (const int*)d_in[2];
    const float* c1_W1  = (const float*)d_in[3];
    const float* c1_b1  = (const float*)d_in[4];
    const float* c1_g1  = (const float*)d_in[5];
    const float* c1_be1 = (const float*)d_in[6];
    const float* c1_W2  = (const float*)d_in[7];
    const float* c1_b2  = (const float*)d_in[8];
    const float* bn1_g  = (const float*)d_in[9];
    const float* bn1_b  = (const float*)d_in[10];
    const float* cs_W1  = (const float*)d_in[11];
    const float* cs_b1  = (const float*)d_in[12];
    const float* cs_g1  = (const float*)d_in[13];
    const float* cs_be1 = (const float*)d_in[14];
    const float* cs_W2  = (const float*)d_in[15];
    const float* cs_b2  = (const float*)d_in[16];
    const float* bns_g  = (const float*)d_in[17];
    const float* bns_b  = (const float*)d_in[18];
    const float* vemb   = (const float*)d_in[19];
    const float* v_W1   = (const float*)d_in[20];
    const float* v_b1   = (const float*)d_in[21];
    const float* v_g1   = (const float*)d_in[22];
    const float* v_be1  = (const float*)d_in[23];
    const float* v_W2   = (const float*)d_in[24];
    const float* v_b2   = (const float*)d_in[25];
    const float* v_g2   = (const float*)d_in[26];
    const float* v_be2  = (const float*)d_in[27];
    float* out = (float*)d_out;

    const int* srcI = ei;
    const int* dstI = ei + NE;

    float *Z, *Hb, *VF;
    __nv_bfloat16 *Whi, *Wlo, *Ahi, *Alo, *Thi, *Tlo, *PLhi, *PLlo, *ZVhi, *ZVlo;
    cudaGetSymbolAddress((void**)&Z,    g_Z);
    cudaGetSymbolAddress((void**)&Hb,   g_Hb);
    cudaGetSymbolAddress((void**)&VF,   g_vf);
    cudaGetSymbolAddress((void**)&Whi,  g_Whi);
    cudaGetSymbolAddress((void**)&Wlo,  g_Wlo);
    cudaGetSymbolAddress((void**)&Ahi,  g_Ahi);
    cudaGetSymbolAddress((void**)&Alo,  g_Alo);
    cudaGetSymbolAddress((void**)&Thi,  g_Thi);
    cudaGetSymbolAddress((void**)&Tlo,  g_Tlo);
    cudaGetSymbolAddress((void**)&PLhi, g_plhi);
    cudaGetSymbolAddress((void**)&PLlo, g_pllo);
    cudaGetSymbolAddress((void**)&ZVhi, g_zvhi);
    cudaGetSymbolAddress((void**)&ZVlo, g_zvlo);

    cudaFuncSetAttribute(k_gemm_mma, cudaFuncAttributeMaxDynamicSharedMemorySize, SM_TOTAL);

    const int TB = 256;
    auto blks = [](int n) { return (n + 255) / 256; };

    // ---- CSR build ----
    k_csr0<<<blks(NN + 1), TB>>>(batch);
    k_deg<<<blks(NE), TB>>>(dstI);
    k_scan<<<1, 1024>>>();
    k_fill<<<blks(NE), TB>>>(srcI, dstI);

    // ---- weight prep ----
    PrepArgs pa;
    pa.src[0] = c1_W1;  pa.K[0] = DD; pa.N[0] = H2; pa.off[0] = OFF_C1W1;
    pa.src[1] = c1_W2;  pa.K[1] = H2; pa.N[1] = HH; pa.off[1] = OFF_C1W2;
    for (int i = 0; i < NL; i++) {
        pa.src[2 + i] = cs_W1 + (size_t)i * HH * H2;
        pa.K[2 + i] = HH; pa.N[2 + i] = H2; pa.off[2 + i] = OFF_CSW1 + (long)i * H2 * HH;
        pa.src[6 + i] = cs_W2 + (size_t)i * H2 * HH;
        pa.K[6 + i] = H2; pa.N[6 + i] = HH; pa.off[6 + i] = OFF_CSW2 + (long)i * H2 * HH;
    }
    pa.src[10] = v_W1; pa.K[10] = HH; pa.N[10] = H2; pa.off[10] = OFF_VW1;
    pa.src[11] = v_W2; pa.K[11] = H2; pa.N[11] = HH; pa.off[11] = OFF_VW2;
    k_prep<<<dim3(4096, 12), TB>>>(pa, Whi, Wlo);

    k_vfinit<<<blks(NG * HH), TB>>>(vemb, VF);

    dim3 gN1(H2 / 128, (NN + 127) / 128);
    dim3 gN2(HH / 128, (NN + 127) / 128);
    dim3 gv1(H2 / 128, 1);
    dim3 gv2(HH / 128, 1);

    // ---- conv1: aggregate x (CSR, no atomics) -> split -> GEMMs ----
    k_aggr1<<<(NN + 3) / 4, 128>>>((const float4*)x, (uint32_t*)Ahi, (uint32_t*)Alo);
    k_gemm_mma<<<gN1, 256, SM_TOTAL>>>(Ahi, Alo, Whi + OFF_C1W1, Wlo + OFF_C1W1,
                                       c1_b1, c1_g1, c1_be1, nullptr, Thi, Tlo,
                                       NN, H2, DD, 1, 1);
    k_gemm_mma<<<gN2, 256, SM_TOTAL>>>(Thi, Tlo, Whi + OFF_C1W2, Wlo + OFF_C1W2,
                                       c1_b2, bn1_g, bn1_b, Hb, nullptr, nullptr,
                                       NN, HH, H2, 1, 0);

    // ---- L GIN layers with virtual node ----
    for (int i = 0; i < NL; i++) {
        k_addv<<<blks(NN * (HH / 4)), TB>>>((const float4*)Hb, (float4*)Z, (const float4*)VF, batch);
        k_aggrH<<<NN, 128>>>((const float4*)Z, (uint32_t*)Ahi, (uint32_t*)Alo);
        k_gemm_mma<<<gN1, 256, SM_TOTAL>>>(Ahi, Alo,
                                           Whi + OFF_CSW1 + (size_t)i * H2 * HH,
                                           Wlo + OFF_CSW1 + (size_t)i * H2 * HH,
                                           cs_b1 + i * H2, cs_g1 + i * H2, cs_be1 + i * H2,
                                           nullptr, Thi, Tlo, NN, H2, HH, 1, 1);
        k_gemm_mma<<<gN2, 256, SM_TOTAL>>>(Thi, Tlo,
                                           Whi + OFF_CSW2 + (size_t)i * H2 * HH,
                                           Wlo + OFF_CSW2 + (size_t)i * H2 * HH,
                                           cs_b2 + i * HH, bns_g + i * HH, bns_b + i * HH,
                                           Hb, nullptr, nullptr, NN, HH, H2,
                                           (i < NL - 1) ? 1 : 0, 0);
        if (i < NL - 1) {
            k_poolv<<<NG, 128>>>((const float4*)Hb, (const float4*)VF,
                                 (uint32_t*)PLhi, (uint32_t*)PLlo);
            k_gemm_mma<<<gv1, 256, SM_TOTAL>>>(PLhi, PLlo, Whi + OFF_VW1, Wlo + OFF_VW1,
                                               v_b1, v_g1, v_be1, nullptr, ZVhi, ZVlo,
                                               NG, H2, HH, 1, 1);
            k_gemm_mma<<<gv2, 256, SM_TOTAL>>>(ZVhi, ZVlo, Whi + OFF_VW2, Wlo + OFF_VW2,
                                               v_b2, v_g2, v_be2, VF, nullptr, nullptr,
                                               NG, HH, H2, 1, 0);
        }
    }

    // ---- readout: mean pool over contiguous ranges ----
    k_poolout<<<NG, 128>>>((const float4*)Hb, (float4*)out);
}